// round 8
// baseline (speedup 1.0000x reference)
#include <cuda_runtime.h>

#define NG      512
#define W_IMG   256
#define H_IMG   256
#define NEG_HALF_LOG2E (-0.7213475204444817f)   // -0.5 * log2(e)
#define LOG2EPS (-27.0f)                        // skip if max alpha < 2^-27

__device__ __forceinline__ float ex2_approx(float x) {
    float y; asm("ex2.approx.f32 %0, %1;" : "=f"(y) : "f"(x)); return y;
}
__device__ __forceinline__ float lg2_approx(float x) {
    float y; asm("lg2.approx.f32 %0, %1;" : "=f"(y) : "f"(x)); return y;
}
__device__ __forceinline__ float rcp_approx(float x) {
    float y; asm("rcp.approx.f32 %0, %1;" : "=f"(y) : "f"(x)); return y;
}

// Per-row compacted render records, built once by prep:
//   gRec[row*2*NG + 2j]   = (mx, ka, kb*dy, kd*dy^2 + log2(op))
//   gRec[row*2*NG + 2j+1] = (cr, cg, cb, 0)
__device__ float4 gRec[H_IMG * 2 * NG];     // 4 MB static
__device__ int    gMrow[H_IMG];

// ── Kernel A: one block per row; thread g owns gaussian g. Full coefficient
//    compute + row-level cull + ordered ballot compaction → global records.
__global__ __launch_bounds__(NG) void prep_kernel(
    const float* __restrict__ means,    // [NG,2]
    const float* __restrict__ cov,      // [NG,2,2]
    const float* __restrict__ opac,     // [NG]
    const float* __restrict__ colors)   // [NG,3]
{
    __shared__ int sCnt[16];
    const int g    = threadIdx.x;
    const int lane = g & 31;
    const int warp = g >> 5;
    const int row  = blockIdx.x;
    const float py = (float)row + 0.5f;

    float4 cv = ((const float4*)cov)[g];          // a, b, c, d
    float2 mn = ((const float2*)means)[g];
    float  op = opac[g];
    float det = fmaf(cv.x, cv.w, -cv.y * cv.z);
    float s   = NEG_HALF_LOG2E * rcp_approx(det);
    float ka  = s * cv.w;                          // < 0
    float kb  = -s * (cv.y + cv.z);
    float kd  = s * cv.x;                          // < 0
    float lop = lg2_approx(op);
    // max over x of the quad form at this dy: q*dy^2 + lop, q = kd - kb^2/(4ka)
    float q   = kd - kb * kb * rcp_approx(4.0f * ka);
    float dy  = py - mn.y;
    bool keep = fmaf(q, dy * dy, lop) > LOG2EPS;

    unsigned ball = __ballot_sync(0xffffffffu, keep);
    if (lane == 0) sCnt[warp] = __popc(ball);
    __syncthreads();
    int base = 0, M = 0;
#pragma unroll
    for (int w = 0; w < 16; w++) {
        int c = sCnt[w];
        if (w < warp) base += c;
        M += c;
    }
    if (keep) {
        int j = base + __popc(ball & ((1u << lane) - 1u));
        float4* rec = gRec + row * (2 * NG);
        rec[2 * j]     = make_float4(mn.x, ka, kb * dy, fmaf(kd * dy, dy, lop));
        rec[2 * j + 1] = make_float4(colors[3 * g + 0], colors[3 * g + 1],
                                     colors[3 * g + 2], 0.0f);
    }
    if (g == 0) gMrow[row] = M;
}

// ── Kernel B: 1024 blocks = (row, x-quarter). 256 threads = 4 groups × 64;
//    each thread composites an ordered quarter of the row's survivors for ONE
//    pixel, reading ready records via __ldg (L1/L2 broadcast). Partials are
//    combined exactly (compositing is an associative affine map).
__global__ __launch_bounds__(256) void Render_75617194213733_kernel(
    float* __restrict__ out)            // [H,W,3]
{
    __shared__ float4 P[3 * 64];        // partials, groups 1..3

    const int tid   = threadIdx.x;
    const int row   = blockIdx.x >> 2;
    const int x0    = (blockIdx.x & 3) << 6;      // 0,64,128,192
    const int group = tid >> 6;
    const int t     = tid & 63;

    const int M  = __ldg(&gMrow[row]);
    const int Mq = (M + 3) >> 2;
    const int j0 = min(group * Mq, M);
    const int j1 = min(j0 + Mq, M);

    const float px = (float)(x0 + t) + 0.5f;
    const float4* __restrict__ rec = gRec + row * (2 * NG);

    float T = 1.0f;
    float r = 0.f, g = 0.f, b = 0.f;

#pragma unroll 4
    for (int j = j0; j < j1; j++) {
        float4 pa = __ldg(&rec[2 * j]);           // mx, ka, kbdy, c1
        float4 pb = __ldg(&rec[2 * j + 1]);       // cr, cg, cb, -
        float dx = px - pa.x;
        float t2 = fmaf(pa.y, dx, pa.z);          // ka*dx + kb*dy
        float m  = fmaf(dx, t2, pa.w);            // folded exponent
        float a  = ex2_approx(m);
        float w  = a * T;
        r = fmaf(w, pb.x, r);
        g = fmaf(w, pb.y, g);
        b = fmaf(w, pb.z, b);
        T *= 1.0000001f - a;                      // (1-a)+1e-7, off the chain
    }

    // Exact segment combine: C = C_a + T_a * C_b (groups 3→2→1→0).
    if (group != 0) P[(group - 1) * 64 + t] = make_float4(r, g, b, T);
    __syncthreads();
    if (group == 0) {
        float4 q1 = P[t], q2 = P[64 + t], q3 = P[128 + t];
        float rr = fmaf(q2.w, q3.x, q2.x);
        float gg = fmaf(q2.w, q3.y, q2.y);
        float bb = fmaf(q2.w, q3.z, q2.z);
        rr = fmaf(q1.w, rr, q1.x);
        gg = fmaf(q1.w, gg, q1.y);
        bb = fmaf(q1.w, bb, q1.z);
        float R = fmaf(T, rr, r);
        float G = fmaf(T, gg, g);
        float B = fmaf(T, bb, b);
        const int base = (row * W_IMG + x0 + t) * 3;
        out[base + 0] = R;
        out[base + 1] = G;
        out[base + 2] = B;
    }
}

extern "C" void kernel_launch(void* const* d_in, const int* in_sizes, int n_in,
                              void* d_out, int out_size) {
    const float* means  = nullptr;
    const float* cov    = nullptr;
    const float* opac   = nullptr;
    const float* colors = nullptr;
    for (int i = 0; i < n_in; i++) {
        switch (in_sizes[i]) {
            case NG * 2: means  = (const float*)d_in[i]; break;
            case NG * 4: cov    = (const float*)d_in[i]; break;
            case NG:     opac   = (const float*)d_in[i]; break;
            case NG * 3: colors = (const float*)d_in[i]; break;
            default: break;
        }
    }
    prep_kernel<<<H_IMG, NG>>>(means, cov, opac, colors);
    Render_75617194213733_kernel<<<4 * H_IMG, 256>>>((float*)d_out);
}

// round 9
// speedup vs baseline: 1.3791x; 1.3791x over previous
#include <cuda_runtime.h>

#define NG      512
#define W_IMG   256
#define H_IMG   256
#define NEG_HALF_LOG2E (-0.7213475204444817f)   // -0.5 * log2(e)
#define LOG2EPS (-27.0f)                        // skip if max alpha < 2^-27

__device__ __forceinline__ float ex2_approx(float x) {
    float y; asm("ex2.approx.f32 %0, %1;" : "=f"(y) : "f"(x)); return y;
}
__device__ __forceinline__ float lg2_approx(float x) {
    float y; asm("lg2.approx.f32 %0, %1;" : "=f"(y) : "f"(x)); return y;
}
__device__ __forceinline__ float rcp_approx(float x) {
    float y; asm("rcp.approx.f32 %0, %1;" : "=f"(y) : "f"(x)); return y;
}

// One block per row, 512 threads = 8 groups × 64; each thread composites an
// ordered eighth of the row's survivors for 4 adjacent pixels (second-
// difference update of the quadratic exponent). Single fused kernel:
// prep (1 gaussian/thread) + row cull + ordered ballot compaction into
// shared, then broadcast-LDS mainloop, then exact affine combine.
__global__ __launch_bounds__(512) void Render_75617194213733_kernel(
    const float* __restrict__ means,    // [NG,2]
    const float* __restrict__ cov,      // [NG,2,2]
    const float* __restrict__ opac,     // [NG]
    const float* __restrict__ colors,   // [NG,3]
    float* __restrict__ out)            // [H,W,3]
{
    __shared__ float4 C[2 * NG];        // [2j]=(mx,ka,kb*dy,kd*dy^2+lop), [2j+1]=(cr,cg,cb,2ka)
    __shared__ float4 P[4][7 * 64];     // per-pixel partials, groups 1..7
    __shared__ int    sCnt[16];

    const int tid  = threadIdx.x;
    const int lane = tid & 31;
    const int warp = tid >> 5;
    const float py = (float)blockIdx.x + 0.5f;

    int M;
    // ── Fused prep + row cull + ordered compacted write (1 gaussian/thread).
    {
        const int g = tid;
        float4 cv = ((const float4*)cov)[g];          // a, b, c, d
        float2 mn = ((const float2*)means)[g];
        float  op = opac[g];
        float det = fmaf(cv.x, cv.w, -cv.y * cv.z);
        float s   = NEG_HALF_LOG2E * rcp_approx(det);
        float ka  = s * cv.w;                          // < 0
        float kb  = -s * (cv.y + cv.z);
        float kd  = s * cv.x;                          // < 0
        float lop = lg2_approx(op);
        // max over x at this dy: q*dy^2 + lop, q = kd - kb^2/(4ka)
        float q   = kd - kb * kb * rcp_approx(4.0f * ka);
        float dy  = py - mn.y;
        bool keep = fmaf(q, dy * dy, lop) > LOG2EPS;

        unsigned ball = __ballot_sync(0xffffffffu, keep);
        if (lane == 0) sCnt[warp] = __popc(ball);
        __syncthreads();
        int base = 0;
        M = 0;
#pragma unroll
        for (int w = 0; w < 16; w++) {
            int c = sCnt[w];
            if (w < warp) base += c;
            M += c;
        }
        if (keep) {
            int j = base + __popc(ball & ((1u << lane) - 1u));
            C[2 * j]     = make_float4(mn.x, ka, kb * dy, fmaf(kd * dy, dy, lop));
            C[2 * j + 1] = make_float4(colors[3 * g + 0], colors[3 * g + 1],
                                       colors[3 * g + 2], ka + ka);
        }
    }
    __syncthreads();

    const int Mq    = (M + 7) >> 3;
    const int group = tid >> 6;           // 0..7
    const int t     = tid & 63;
    const int j0    = min(group * Mq, M);
    const int j1    = min(j0 + Mq, M);

    const float px = (float)(4 * t) + 0.5f;

    float T0 = 1.f, T1 = 1.f, T2 = 1.f, T3 = 1.f;
    float r0 = 0.f, g0 = 0.f, b0 = 0.f;
    float r1 = 0.f, g1 = 0.f, b1 = 0.f;
    float r2 = 0.f, g2 = 0.f, b2 = 0.f;
    float r3 = 0.f, g3 = 0.f, b3 = 0.f;

#pragma unroll 2
    for (int j = j0; j < j1; j++) {
        float4 pa = C[2 * j];               // mx, ka, kbdy, c1
        float4 pb = C[2 * j + 1];           // cr, cg, cb, 2ka
        float dx = px - pa.x;
        float t2 = fmaf(pa.y, dx, pa.z);            // ka*dx + kb*dy
        float m0 = fmaf(dx, t2, pa.w);              // exponent at px
        float s0 = t2 + fmaf(pa.y, dx, pa.y);       // first difference
        float m1 = m0 + s0;
        float s1 = s0 + pb.w;                       // second difference = 2ka
        float m2 = m1 + s1;
        float s2 = s1 + pb.w;
        float m3 = m2 + s2;

        float a0 = ex2_approx(m0);
        float a1 = ex2_approx(m1);
        float a2 = ex2_approx(m2);
        float a3 = ex2_approx(m3);

        float w0 = a0 * T0, w1 = a1 * T1, w2 = a2 * T2, w3 = a3 * T3;
        r0 = fmaf(w0, pb.x, r0); g0 = fmaf(w0, pb.y, g0); b0 = fmaf(w0, pb.z, b0);
        r1 = fmaf(w1, pb.x, r1); g1 = fmaf(w1, pb.y, g1); b1 = fmaf(w1, pb.z, b1);
        r2 = fmaf(w2, pb.x, r2); g2 = fmaf(w2, pb.y, g2); b2 = fmaf(w2, pb.z, b2);
        r3 = fmaf(w3, pb.x, r3); g3 = fmaf(w3, pb.y, g3); b3 = fmaf(w3, pb.z, b3);
        T0 *= 1.0000001f - a0;              // (1-a)+1e-7, off the critical chain
        T1 *= 1.0000001f - a1;
        T2 *= 1.0000001f - a2;
        T3 *= 1.0000001f - a3;
    }

    // ── Exact segment combine: C = C_a + T_a * C_b (fold groups 7→…→0).
    if (group != 0) {
        int pi = (group - 1) * 64 + t;
        P[0][pi] = make_float4(r0, g0, b0, T0);
        P[1][pi] = make_float4(r1, g1, b1, T1);
        P[2][pi] = make_float4(r2, g2, b2, T2);
        P[3][pi] = make_float4(r3, g3, b3, T3);
    }
    __syncthreads();
    if (group == 0) {
        float rl[4] = {r0, r1, r2, r3};
        float gl[4] = {g0, g1, g2, g3};
        float bl[4] = {b0, b1, b2, b3};
        float Tl[4] = {T0, T1, T2, T3};
        float R[4], G[4], B[4];
#pragma unroll
        for (int p = 0; p < 4; p++) {
            float4 q = P[p][6 * 64 + t];        // group 7 partial
            float rr = q.x, gg = q.y, bb = q.z;
            float TT = q.w;
#pragma unroll
            for (int k = 5; k >= 0; k--) {      // fold groups 6..1
                float4 u = P[p][k * 64 + t];
                rr = fmaf(u.w, rr, u.x);
                gg = fmaf(u.w, gg, u.y);
                bb = fmaf(u.w, bb, u.z);
            }
            R[p] = fmaf(Tl[p], rr, rl[p]);
            G[p] = fmaf(Tl[p], gg, gl[p]);
            B[p] = fmaf(Tl[p], bb, bl[p]);
        }
        // 4 px × RGB = 12 floats, 16B-aligned (48-byte stride per thread).
        float4* o4 = (float4*)(out + (blockIdx.x * W_IMG + 4 * t) * 3);
        o4[0] = make_float4(R[0], G[0], B[0], R[1]);
        o4[1] = make_float4(G[1], B[1], R[2], G[2]);
        o4[2] = make_float4(B[2], R[3], G[3], B[3]);
    }
}

extern "C" void kernel_launch(void* const* d_in, const int* in_sizes, int n_in,
                              void* d_out, int out_size) {
    const float* means  = nullptr;
    const float* cov    = nullptr;
    const float* opac   = nullptr;
    const float* colors = nullptr;
    for (int i = 0; i < n_in; i++) {
        switch (in_sizes[i]) {
            case NG * 2: means  = (const float*)d_in[i]; break;
            case NG * 4: cov    = (const float*)d_in[i]; break;
            case NG:     opac   = (const float*)d_in[i]; break;
            case NG * 3: colors = (const float*)d_in[i]; break;
            default: break;
        }
    }
    Render_75617194213733_kernel<<<H_IMG, 512>>>(means, cov, opac, colors,
                                                 (float*)d_out);
}

// round 10
// speedup vs baseline: 1.7048x; 1.2362x over previous
#include <cuda_runtime.h>

#define NG      512
#define W_IMG   256
#define H_IMG   256
#define NEG_HALF_LOG2E (-0.7213475204444817f)   // -0.5 * log2(e)
#define LOG2EPS (-27.0f)                        // skip if max alpha < 2^-27

__device__ __forceinline__ float ex2_approx(float x) {
    float y; asm("ex2.approx.f32 %0, %1;" : "=f"(y) : "f"(x)); return y;
}
__device__ __forceinline__ float lg2_approx(float x) {
    float y; asm("lg2.approx.f32 %0, %1;" : "=f"(y) : "f"(x)); return y;
}
__device__ __forceinline__ float rcp_approx(float x) {
    float y; asm("rcp.approx.f32 %0, %1;" : "=f"(y) : "f"(x)); return y;
}

// One block per row, 256 threads = 4 groups × 64; each thread composites an
// ordered quarter of the row's survivors for 4 adjacent pixels (second-
// difference update of the quadratic exponent). Warp-uniform early-skip
// drops the MUFU+composite work when a gaussian is negligible across the
// warp's whole 128-px window. Partials combined exactly at the end.
__global__ __launch_bounds__(256) void Render_75617194213733_kernel(
    const float* __restrict__ means,    // [NG,2]
    const float* __restrict__ cov,      // [NG,2,2]
    const float* __restrict__ opac,     // [NG]
    const float* __restrict__ colors,   // [NG,3]
    float* __restrict__ out)            // [H,W,3]
{
    __shared__ float4 C[2 * NG];        // [2j]=(mx,ka,kb*dy,kd*dy^2+lop), [2j+1]=(cr,cg,cb,2ka)
    __shared__ float4 Ppart[4][3 * 64]; // per-pixel partials, groups 1..3
    __shared__ int    sCnt[16];
    __shared__ int    sBase[16];
    __shared__ int    sMtot;

    const int tid  = threadIdx.x;
    const int lane = tid & 31;
    const int warp = tid >> 5;
    const float py = (float)blockIdx.x + 0.5f;

    // ── Fused prep + row cull (2 gaussians/thread).
    float4 A[2];  // mx, ka, kbdy, c1
    float4 B[2];  // cr, cg, cb, 2ka
    bool   kp[2];
    unsigned bl[2];
#pragma unroll
    for (int c = 0; c < 2; c++) {
        const int g = tid + 256 * c;
        float4 cv = ((const float4*)cov)[g];
        float2 mn = ((const float2*)means)[g];
        float  op = opac[g];
        float det = fmaf(cv.x, cv.w, -cv.y * cv.z);
        float s   = NEG_HALF_LOG2E * rcp_approx(det);
        float ka  = s * cv.w;
        float kb  = -s * (cv.y + cv.z);
        float kd  = s * cv.x;
        float lop = lg2_approx(op);
        float q   = kd - kb * kb * rcp_approx(4.0f * ka);
        float dy  = py - mn.y;
        kp[c] = fmaf(q, dy * dy, lop) > LOG2EPS;
        bl[c] = __ballot_sync(0xffffffffu, kp[c]);
        if (lane == 0) sCnt[c * 8 + warp] = __popc(bl[c]);
        A[c] = make_float4(mn.x, ka, kb * dy, fmaf(kd * dy, dy, lop));
        B[c] = make_float4(colors[3 * g + 0], colors[3 * g + 1],
                           colors[3 * g + 2], ka + ka);
    }
    __syncthreads();

    // ── Warp-0 shuffle scan of the 16 (chunk, warp) counts.
    if (warp == 0) {
        int c = (lane < 16) ? sCnt[lane] : 0;
        int inc = c;
#pragma unroll
        for (int d = 1; d < 16; d <<= 1) {
            int n = __shfl_up_sync(0xffffffffu, inc, d);
            if (lane >= d) inc += n;
        }
        if (lane < 16) sBase[lane] = inc - c;
        if (lane == 15) sMtot = inc;
    }
    __syncthreads();

    const int M = sMtot;
    if (kp[0]) {
        int j = sBase[warp] + __popc(bl[0] & ((1u << lane) - 1u));
        C[2 * j] = A[0];  C[2 * j + 1] = B[0];
    }
    if (kp[1]) {
        int j = sBase[8 + warp] + __popc(bl[1] & ((1u << lane) - 1u));
        C[2 * j] = A[1];  C[2 * j + 1] = B[1];
    }
    __syncthreads();

    const int Mq    = (M + 3) >> 2;
    const int group = tid >> 6;
    const int t     = tid & 63;
    const int j0    = min(group * Mq, M);
    const int j1    = min(j0 + Mq, M);

    const float px = (float)(4 * t) + 0.5f;

    float T0 = 1.f, T1 = 1.f, T2 = 1.f, T3 = 1.f;
    float r0 = 0.f, g0 = 0.f, b0 = 0.f;
    float r1 = 0.f, g1 = 0.f, b1 = 0.f;
    float r2 = 0.f, g2 = 0.f, b2 = 0.f;
    float r3 = 0.f, g3 = 0.f, b3 = 0.f;

#pragma unroll 2
    for (int j = j0; j < j1; j++) {
        float4 pa = C[2 * j];           // mx, ka, kbdy, c1
        float4 pb = C[2 * j + 1];       // cr, cg, cb, 2ka
        float dx = px - pa.x;
        float t2 = fmaf(pa.y, dx, pa.z);          // ka*dx + kb*dy
        float m0 = fmaf(dx, t2, pa.w);            // exponent at px
        float s0 = t2 + fmaf(pa.y, dx, pa.y);     // first difference
        float m1 = m0 + s0;
        float s1 = s0 + pb.w;                     // second difference = 2ka
        float m2 = m1 + s1;
        float s2 = s1 + pb.w;
        float m3 = m2 + s2;

        // Warp-uniform skip: exponent is concave in x, so the max over this
        // thread's 4 pixels is max(m0, m3) region-wise; use all four anyway.
        float mm = fmaxf(fmaxf(m0, m1), fmaxf(m2, m3));
        if (__any_sync(0xffffffffu, mm > LOG2EPS)) {
            float a0 = ex2_approx(m0);
            float a1 = ex2_approx(m1);
            float a2 = ex2_approx(m2);
            float a3 = ex2_approx(m3);

            float w0 = a0 * T0, w1 = a1 * T1, w2 = a2 * T2, w3 = a3 * T3;
            r0 = fmaf(w0, pb.x, r0); g0 = fmaf(w0, pb.y, g0); b0 = fmaf(w0, pb.z, b0);
            r1 = fmaf(w1, pb.x, r1); g1 = fmaf(w1, pb.y, g1); b1 = fmaf(w1, pb.z, b1);
            r2 = fmaf(w2, pb.x, r2); g2 = fmaf(w2, pb.y, g2); b2 = fmaf(w2, pb.z, b2);
            r3 = fmaf(w3, pb.x, r3); g3 = fmaf(w3, pb.y, g3); b3 = fmaf(w3, pb.z, b3);
            T0 *= 1.0000001f - a0;      // (1-a)+1e-7, off the critical chain
            T1 *= 1.0000001f - a1;
            T2 *= 1.0000001f - a2;
            T3 *= 1.0000001f - a3;
        }
    }

    // ── Exact segment combine: C = C_a + T_a * C_b (fold groups 3→2→1→0).
    if (group != 0) {
        int pi = (group - 1) * 64 + t;
        Ppart[0][pi] = make_float4(r0, g0, b0, T0);
        Ppart[1][pi] = make_float4(r1, g1, b1, T1);
        Ppart[2][pi] = make_float4(r2, g2, b2, T2);
        Ppart[3][pi] = make_float4(r3, g3, b3, T3);
    }
    __syncthreads();
    if (group == 0) {
        float rl[4] = {r0, r1, r2, r3};
        float gl[4] = {g0, g1, g2, g3};
        float bl_[4] = {b0, b1, b2, b3};
        float Tl[4] = {T0, T1, T2, T3};
        float R[4], G[4], B[4];
#pragma unroll
        for (int p = 0; p < 4; p++) {
            float4 q1 = Ppart[p][t];
            float4 q2 = Ppart[p][64 + t];
            float4 q3 = Ppart[p][128 + t];
            float rr = fmaf(q2.w, q3.x, q2.x);
            float gg = fmaf(q2.w, q3.y, q2.y);
            float bb = fmaf(q2.w, q3.z, q2.z);
            rr = fmaf(q1.w, rr, q1.x);
            gg = fmaf(q1.w, gg, q1.y);
            bb = fmaf(q1.w, bb, q1.z);
            R[p] = fmaf(Tl[p], rr, rl[p]);
            G[p] = fmaf(Tl[p], gg, gl[p]);
            B[p] = fmaf(Tl[p], bb, bl_[p]);
        }
        float4* o4 = (float4*)(out + (blockIdx.x * W_IMG + 4 * t) * 3);
        o4[0] = make_float4(R[0], G[0], B[0], R[1]);
        o4[1] = make_float4(G[1], B[1], R[2], G[2]);
        o4[2] = make_float4(B[2], R[3], G[3], B[3]);
    }
}

extern "C" void kernel_launch(void* const* d_in, const int* in_sizes, int n_in,
                              void* d_out, int out_size) {
    const float* means  = nullptr;
    const float* cov    = nullptr;
    const float* opac   = nullptr;
    const float* colors = nullptr;
    for (int i = 0; i < n_in; i++) {
        switch (in_sizes[i]) {
            case NG * 2: means  = (const float*)d_in[i]; break;
            case NG * 4: cov    = (const float*)d_in[i]; break;
            case NG:     opac   = (const float*)d_in[i]; break;
            case NG * 3: colors = (const float*)d_in[i]; break;
            default: break;
        }
    }
    Render_75617194213733_kernel<<<H_IMG, 256>>>(means, cov, opac, colors,
                                                 (float*)d_out);
}